// round 16
// baseline (speedup 1.0000x reference)
#include <cuda_runtime.h>
#include <cuda_fp16.h>
#include <cstdint>

// VQ: B=16, N=4096, D=128, M=2048
// out layout (float32): quantized_st[8388608], loss[1], perp[1], indices[65536]

#define BN_TOTAL 65536
#define M_CB     2048
#define D_DIM    128
#define Q_ELEMS  8388608
#define LOSS_OFF 8388608
#define PERP_OFF 8388609
#define IDX_OFF  8388610

#define ROW_PITCH   272u                 // 136 fp16 per row (128 data + 8 pad)
#define SPLIT_BYTES (M_CB * ROW_PITCH)   // 557056 (hi split image only)
#define B_TILE      34816u               // 128 rows * 272
#define B_HALF      17408u               // 64 rows * 272 (per group half)
#define NUM_NT      16

#define MARGIN      0.02f                // ~18 sigma of hh-only approx dist error
#define U64MAX      0xFFFFFFFFFFFFFFFFull

// SMEM map (bytes). A hi image (17408) OVERLAYS B buf0 start.
#define SM_AB     0u                     // 2 B bufs * 34816 = 69632
#define SM_L2K    69632u                 // 8192
#define SM_L2Q    77824u                 // 256
#define SM_CAND   78080u                 // 64 rows * 32 u64 = 16384
#define SM_BEST   94464u                 // 256
#define SM_WSUM   94720u                 // 32
#define SM_TOTAL  94752u

__device__ float g_l2k[M_CB];
__device__ int   g_counts[M_CB];
__device__ float g_loss;
__device__ __align__(256) unsigned char g_wsplit[SPLIT_BYTES];

// ---------------------------------------------------------------------------
__device__ __forceinline__ uint32_t smem_to_u32(const void* p) {
    uint32_t a;
    asm("{ .reg .u64 t; cvta.to.shared.u64 t, %1; cvt.u32.u64 %0, t; }"
        : "=r"(a) : "l"(p));
    return a;
}
__device__ __forceinline__ void cp16(uint32_t dst, const void* src) {
    asm volatile("cp.async.cg.shared.global [%0], [%1], 16;"
                 :: "r"(dst), "l"(src) : "memory");
}
__device__ __forceinline__ void cp_commit() {
    asm volatile("cp.async.commit_group;" ::: "memory");
}
__device__ __forceinline__ void cp_wait0() {
    asm volatile("cp.async.wait_group 0;" ::: "memory");
}
__device__ __forceinline__ void barg(int id) {
    asm volatile("bar.sync %0, 128;" :: "r"(id) : "memory");
}
__device__ __forceinline__ void ldsm4(uint32_t* r, uint32_t addr) {
    asm volatile("ldmatrix.sync.aligned.m8n8.x4.shared.b16 {%0,%1,%2,%3}, [%4];"
                 : "=r"(r[0]), "=r"(r[1]), "=r"(r[2]), "=r"(r[3]) : "r"(addr));
}
__device__ __forceinline__ void mma_f16(float* d, const uint32_t* a, const uint32_t* b) {
    asm volatile(
        "mma.sync.aligned.m16n8k16.row.col.f32.f16.f16.f32 "
        "{%0,%1,%2,%3}, {%4,%5,%6,%7}, {%8,%9}, {%0,%1,%2,%3};"
        : "+f"(d[0]), "+f"(d[1]), "+f"(d[2]), "+f"(d[3])
        : "r"(a[0]), "r"(a[1]), "r"(a[2]), "r"(a[3]), "r"(b[0]), "r"(b[1]));
}
// branchless packed top-4 insert: p = (float_bits << 32) | index.
// dists are all >> 0 so unsigned u64 order == (value, index) lexicographic.
__device__ __forceinline__ void t4ins(unsigned long long* t, unsigned long long p) {
    unsigned long long a0 = p  < t[0] ? p    : t[0];
    unsigned long long b0 = p  < t[0] ? t[0] : p;
    t[0] = a0;
    unsigned long long a1 = b0 < t[1] ? b0   : t[1];
    unsigned long long b1 = b0 < t[1] ? t[1] : b0;
    t[1] = a1;
    unsigned long long a2 = b1 < t[2] ? b1   : t[2];
    unsigned long long b2 = b1 < t[2] ? t[2] : b1;
    t[2] = a2;
    t[3] = b2 < t[3] ? b2 : t[3];
}

// ---------------------------------------------------------------------------
// prep: codebook hi fp16 image + ||k||^2 (strict sequential, spread across
// all blocks) + zeroing
// ---------------------------------------------------------------------------
__global__ void prep_kernel(const float* __restrict__ w) {
    const int oct = blockIdx.x * 256 + threadIdx.x;   // 0..32767
    {
        int n = oct >> 4, k0 = (oct & 15) << 3;
        const float* src = w + (size_t)n * D_DIM + k0;
        __align__(16) __half hi[8];
#pragma unroll
        for (int j = 0; j < 8; j++) hi[j] = __float2half_rn(src[j]);
        uint32_t off = (uint32_t)n * ROW_PITCH + (uint32_t)k0 * 2;
        *(uint4*)(g_wsplit + off) = *(uint4*)hi;
    }
    // l2k: 16 rows per block, spread over all 128 blocks (same per-row math)
    if (threadIdx.x < 16) {
        int row = blockIdx.x * 16 + threadIdx.x;
        const float* wr = w + (size_t)row * D_DIM;
        float s = 0.f;
        for (int i = 0; i < D_DIM; i++)
            s = __fadd_rn(s, __fmul_rn(wr[i], wr[i]));   // strict sequential
        g_l2k[row] = s;
    }
    if (oct < M_CB) g_counts[oct] = 0;
    if (oct == 0)   g_loss = 0.f;
}

// ---------------------------------------------------------------------------
// each 128-thread group loads ONLY its own 64-row half of a 128-row B tile
__device__ __forceinline__ void load_b_half(uint32_t sb, int buf, int nt,
                                            int grp, int gt) {
    const unsigned char* src = g_wsplit + (size_t)nt * B_TILE + (size_t)grp * B_HALF;
    uint32_t dst = sb + SM_AB + (uint32_t)buf * B_TILE + (uint32_t)grp * B_HALF;
    for (int i = gt; i < (int)(B_HALF / 16); i += 128)
        cp16(dst + (uint32_t)i * 16u, src + (size_t)i * 16);
}

__device__ __forceinline__ float exact_dist(const float* __restrict__ xrow,
                                            const float* __restrict__ w,
                                            int n, float l2q, float l2k) {
    const float4* wr = (const float4*)(w + (size_t)n * D_DIM);
    const float4* xr = (const float4*)xrow;
    float ps = 0.f;
#pragma unroll
    for (int i = 0; i < 32; i++) {
        float4 a = xr[i], b = wr[i];
        ps = __fmaf_rn(a.x, b.x, ps);
        ps = __fmaf_rn(a.y, b.y, ps);
        ps = __fmaf_rn(a.z, b.z, ps);
        ps = __fmaf_rn(a.w, b.w, ps);
    }
    return __fmaf_rn(-2.f, ps, __fadd_rn(l2q, l2k));
}

// ---------------------------------------------------------------------------
// main: M=64 query tile per CTA, 256 threads (8 warps, 4(M) x 2(N)),
// 2 CTAs/SM. hh-only fp16 HMMA sweep, N_TILE=128 (16 iterations: per-tile
// overhead amortized 2x), per-thread top-4 capture per row-half; exact
// fp32 refine for near rows; epilogue.
// ---------------------------------------------------------------------------
__global__ __launch_bounds__(256, 2)
void vq_main_kernel(const float* __restrict__ x, const float* __restrict__ w,
                    float* __restrict__ out)
{
    extern __shared__ char smem[];
    const uint32_t sb = smem_to_u32(smem);
    const int tid = threadIdx.x;
    const int wid = tid >> 5, l = tid & 31;
    const int wx = wid & 3, wy = wid >> 2;        // wx: M (4 x 16 rows), wy: N group
    const int lq = l >> 2, lr = l & 3;
    const int m0 = blockIdx.x * 64;
    const int grp = wy;                            // group id == tid>>7
    const int gt  = tid & 127;                     // thread id within group
    const int phase = (blockIdx.x & 1) << 3;       // co-resident CTA stagger (8 of 16)

    float* l2k_s  = (float*)(smem + SM_L2K);
    float* l2q_s  = (float*)(smem + SM_L2Q);
    unsigned long long* cand = (unsigned long long*)(smem + SM_CAND);  // [64][32]
    int*   best_s = (int*)  (smem + SM_BEST);
    float* wsum   = (float*)(smem + SM_WSUM);

    // ---- build A hi image (fp16) in B-buf0 region (overlay)
#pragma unroll
    for (int i = 0; i < 4; i++) {
        int idx = tid + (i << 8);               // 0..1023 octets (64 rows x 16)
        int r = idx >> 4, k0 = (idx & 15) << 3;
        const float4* src = (const float4*)(x + (size_t)(m0 + r) * D_DIM + k0);
        float4 v0 = src[0], v1 = src[1];
        float vv[8] = {v0.x, v0.y, v0.z, v0.w, v1.x, v1.y, v1.z, v1.w};
        __align__(16) __half hi[8];
#pragma unroll
        for (int j = 0; j < 8; j++) hi[j] = __float2half_rn(vv[j]);
        uint32_t off = SM_AB + (uint32_t)r * ROW_PITCH + (uint32_t)k0 * 2;
        *(uint4*)(smem + off) = *(uint4*)hi;
    }
    // ---- stage l2k (512 float4 = 2048 floats)
    ((float4*)l2k_s)[tid]       = ((const float4*)g_l2k)[tid];
    ((float4*)l2k_s)[tid + 256] = ((const float4*)g_l2k)[tid + 256];
    // ---- l2q per row: strict sequential fp32 (reference rounding)
    if (tid < 64) {
        const float* xr = x + (size_t)(m0 + tid) * D_DIM;
        float s = 0.f;
        for (int k = 0; k < D_DIM; k++)
            s = __fadd_rn(s, __fmul_rn(xr[k], xr[k]));
        l2q_s[tid] = s;
    }
    __syncthreads();     // A image visible

    // ---- load A fragments ONCE (register-resident: 8 chunks x 4 regs)
    uint32_t aF[8][4];
    {
        uint32_t row = (uint32_t)(wx * 16) + (uint32_t)(l & 15);
        uint32_t kbl = (uint32_t)((l >> 4) & 1) * 16u;
        uint32_t base = sb + SM_AB + row * ROW_PITCH + kbl;
#pragma unroll
        for (int c = 0; c < 8; c++)
            ldsm4(aF[c], base + (uint32_t)c * 32u);
    }
    float lqr[2];
    lqr[0] = l2q_s[wx * 16 + lq];
    lqr[1] = l2q_s[wx * 16 + lq + 8];
    __syncthreads();     // A image consumed -> buf0 free for B

    // first B tile (phase-staggered) into buf0, per group half
    load_b_half(sb, 0, phase, grp, gt);
    cp_commit();

    // B lane base (within own group's 64-row half); buf offset added per tile
    uint32_t bBase;
    {
        uint32_t row = (uint32_t)(l & 7) + (uint32_t)((l >> 4) & 1) * 8u;
        uint32_t kbl = (uint32_t)((l >> 3) & 1) * 16u;
        bBase = sb + SM_AB + (uint32_t)grp * B_HALF + row * ROW_PITCH + kbl;
    }

    // per-thread top-4 per row-half
    unsigned long long t4[2][4];
#pragma unroll
    for (int h = 0; h < 2; h++)
#pragma unroll
        for (int j = 0; j < 4; j++) t4[h][j] = U64MAX;
    float f4[2] = {3.0e38f, 3.0e38f};   // fp32 shadow of 4th-best values

    for (int it = 0; it < NUM_NT; it++) {
        const int nt = (it + phase) & 15;          // actual tile id
        cp_wait0();          // this group's tile it arrived
        barg(1 + grp);       // group-local: data visible; group done with
                             // the buffer about to be overwritten below
        if (it + 1 < NUM_NT) {
            load_b_half(sb, (it + 1) & 1, (nt + 1) & 15, grp, gt);
            cp_commit();
        }

        float acc[8][4];
#pragma unroll
        for (int n8 = 0; n8 < 8; n8++)
#pragma unroll
            for (int q = 0; q < 4; q++) acc[n8][q] = 0.f;

        const uint32_t bOff = (uint32_t)(it & 1) * B_TILE;

#pragma unroll
        for (int c = 0; c < 8; c++) {
            const uint32_t kb = (uint32_t)c * 32u;
            uint32_t bF[4][4];    // [ni16 group of 16 rows][reg]
#pragma unroll
            for (int g = 0; g < 4; g++)
                ldsm4(bF[g], bBase + bOff + (uint32_t)g * (16u * ROW_PITCH) + kb);
#pragma unroll
            for (int n8 = 0; n8 < 8; n8++)
                mma_f16(acc[n8], aF[c], &bF[n8 >> 1][(n8 & 1) * 2]);
        }

        // epilogue per row-half: 16 dists -> tile-min guard -> rare top-4
        // insert. Skip is exact: all v > f4 strictly implies every packed
        // key > t[3] (positive-float bit monotonicity) -> inserts no-ops.
        const int base = nt * 128 + wy * 64 + (lr << 1);
#pragma unroll
        for (int h = 0; h < 2; h++) {
            float vv[16];
#pragma unroll
            for (int n8 = 0; n8 < 8; n8++) {
                const int col0 = base + n8 * 8;
                const float2 lk = *(const float2*)(l2k_s + col0);
                vv[n8 * 2 + 0] = __fmaf_rn(-2.f, acc[n8][h * 2 + 0],
                                           __fadd_rn(lqr[h], lk.x));
                vv[n8 * 2 + 1] = __fmaf_rn(-2.f, acc[n8][h * 2 + 1],
                                           __fadd_rn(lqr[h], lk.y));
            }
            float tm = vv[0];
#pragma unroll
            for (int j = 1; j < 16; j++) tm = fminf(tm, vv[j]);
            if (tm <= f4[h]) {
#pragma unroll
                for (int j = 0; j < 16; j++) {
                    unsigned n = (unsigned)(base + ((j >> 1) << 3) + (j & 1));
                    unsigned long long p =
                        ((unsigned long long)__float_as_uint(vv[j]) << 32) | n;
                    t4ins(t4[h], p);
                }
                f4[h] = __uint_as_float((uint32_t)(t4[h][3] >> 32));
            }
        }
        // no trailing barrier: next iteration's group barrier protects reuse
    }

    // ---- write per-thread top-4 candidates (no lane merge: keep all 32/row)
#pragma unroll
    for (int h = 0; h < 2; h++) {
        int row = wx * 16 + h * 8 + lq;
        unsigned long long* dst = cand + row * 32 + wy * 16 + lr * 4;
#pragma unroll
        for (int j = 0; j < 4; j++) dst[j] = t4[h][j];
    }
    __syncthreads();    // both groups' cand slots visible

    // ---- per-row final scan: approx top-2 gap test + exact fp32 refine
    if (tid < 64) {
        unsigned long long b1 = U64MAX, b2 = U64MAX;
        const unsigned long long* cr = cand + tid * 32;
#pragma unroll
        for (int j = 0; j < 32; j++) {
            unsigned long long p = cr[j];
            unsigned long long mx = p > b1 ? p : b1;
            b1 = p < b1 ? p : b1;
            b2 = mx < b2 ? mx : b2;
        }
        float v1 = __uint_as_float((uint32_t)(b1 >> 32));
        float v2 = __uint_as_float((uint32_t)(b2 >> 32));
        int best = (int)(uint32_t)(b1 & 0xFFFFFFFFu);
        if (v2 - v1 <= MARGIN) {
            const float* xrow = x + (size_t)(m0 + tid) * D_DIM;
            const float l2q_r = l2q_s[tid];
            float bd = 3.0e38f;
            int   bi = 0x7fffffff;
#pragma unroll 1
            for (int j = 0; j < 32; j++) {
                unsigned long long p = cr[j];
                float pv = __uint_as_float((uint32_t)(p >> 32));
                if (pv <= v1 + MARGIN) {
                    int n = (int)(uint32_t)(p & 0xFFFFFFFFu);
                    float d = exact_dist(xrow, w, n, l2q_r, l2k_s[n]);
                    if (d < bd || (d == bd && n < bi)) { bd = d; bi = n; }
                }
            }
            best = bi;
        }
        best_s[tid] = best;
        atomicAdd(&g_counts[best], 1);
        out[IDX_OFF + m0 + tid] = (float)best;
    }
    __syncthreads();

    // ---- gather z, quantized_st = x + (z - x), loss partial (quarter-row/thread)
    {
        const int r  = tid >> 2;
        const int kb = (tid & 3) << 5;
        const int best = best_s[r];
        const float4* xr = (const float4*)(x + (size_t)(m0 + r) * D_DIM + kb);
        const float4* wz = (const float4*)(w + (size_t)best * D_DIM + kb);
        float4* oq = (float4*)(out + (size_t)(m0 + r) * D_DIM + kb);
        float lsum = 0.f;
#pragma unroll
        for (int i = 0; i < 8; i++) {
            float4 xv = xr[i], z = wz[i];
            float4 qv;
            qv.x = __fadd_rn(xv.x, __fsub_rn(z.x, xv.x));
            qv.y = __fadd_rn(xv.y, __fsub_rn(z.y, xv.y));
            qv.z = __fadd_rn(xv.z, __fsub_rn(z.z, xv.z));
            qv.w = __fadd_rn(xv.w, __fsub_rn(z.w, xv.w));
            oq[i] = qv;
            float d0 = __fsub_rn(qv.x, xv.x), d1 = __fsub_rn(qv.y, xv.y);
            float d2 = __fsub_rn(qv.z, xv.z), d3 = __fsub_rn(qv.w, xv.w);
            lsum += d0 * d0 + d1 * d1 + d2 * d2 + d3 * d3;
        }
#pragma unroll
        for (int o = 16; o > 0; o >>= 1)
            lsum += __shfl_down_sync(0xffffffffu, lsum, o);
        if ((tid & 31) == 0) wsum[wid] = lsum;
    }
    __syncthreads();
    if (tid == 0) {
        float s = 0.f;
#pragma unroll
        for (int i = 0; i < 8; i++) s += wsum[i];
        atomicAdd(&g_loss, s);
    }
}

// ---------------------------------------------------------------------------
// finalize: loss mean + perplexity
// ---------------------------------------------------------------------------
__global__ void finalize_kernel(float* __restrict__ out) {
    int t = threadIdx.x;
    float s = 0.f;
    for (int i = t; i < M_CB; i += 256) {
        float p = (float)g_counts[i] * (1.0f / 65536.0f);
        s += p * logf(p + 1e-10f);
    }
#pragma unroll
    for (int o = 16; o > 0; o >>= 1)
        s += __shfl_down_sync(0xffffffffu, s, o);
    __shared__ float ws[8];
    if ((t & 31) == 0) ws[t >> 5] = s;
    __syncthreads();
    if (t == 0) {
        float tot = 0.f;
#pragma unroll
        for (int i = 0; i < 8; i++) tot += ws[i];
        out[LOSS_OFF] = g_loss * (1.0f / 8388608.0f);
        out[PERP_OFF] = expf(-tot);
    }
}

// ---------------------------------------------------------------------------
extern "C" void kernel_launch(void* const* d_in, const int* in_sizes, int n_in,
                              void* d_out, int out_size) {
    const float* x = (const float*)d_in[0];
    const float* w = (const float*)d_in[1];
    if (n_in >= 2 && in_sizes[0] == M_CB * D_DIM && in_sizes[1] == Q_ELEMS) {
        x = (const float*)d_in[1];
        w = (const float*)d_in[0];
    }
    float* out = (float*)d_out;

    cudaFuncSetAttribute(vq_main_kernel,
                         cudaFuncAttributeMaxDynamicSharedMemorySize, SM_TOTAL);

    prep_kernel<<<128, 256>>>(w);
    vq_main_kernel<<<BN_TOTAL / 64, 256, SM_TOTAL>>>(x, w, out);
    finalize_kernel<<<1, 256>>>(out);
}

// round 17
// speedup vs baseline: 1.5230x; 1.5230x over previous
#include <cuda_runtime.h>
#include <cuda_fp16.h>
#include <cstdint>

// VQ: B=16, N=4096, D=128, M=2048
// out layout (float32): quantized_st[8388608], loss[1], perp[1], indices[65536]

#define BN_TOTAL 65536
#define M_CB     2048
#define D_DIM    128
#define Q_ELEMS  8388608
#define LOSS_OFF 8388608
#define PERP_OFF 8388609
#define IDX_OFF  8388610

#define ROW_PITCH   272u                 // 136 fp16 per row (128 data + 8 pad)
#define SPLIT_BYTES (M_CB * ROW_PITCH)   // 557056 (hi split image only)
#define B_SPLIT     17408u               // 64 rows * 272 (one tile)
#define B_HALF      8704u                // 32 rows * 272 (per group half)
#define B_BUF       17408u               // one buffer = one tile
#define NUM_NT      32
#define NUM_PAIRS   16

#define MARGIN      0.02f                // ~18 sigma of hh-only approx dist error
#define U64MAX      0xFFFFFFFFFFFFFFFFull

// SMEM map (bytes). A hi image (17408) OVERLAYS B buf0. 4 B buffers.
#define SM_AB     0u                     // 4 bufs * 17408 = 69632
#define SM_L2K    69632u                 // 8192
#define SM_L2Q    77824u                 // 256
#define SM_CAND   78080u                 // 64 rows * 32 u64 = 16384
#define SM_BEST   94464u                 // 256
#define SM_WSUM   94720u                 // 32
#define SM_TOTAL  94752u

__device__ float g_l2k[M_CB];
__device__ int   g_counts[M_CB];
__device__ float g_loss;
__device__ __align__(256) unsigned char g_wsplit[SPLIT_BYTES];

// ---------------------------------------------------------------------------
__device__ __forceinline__ uint32_t smem_to_u32(const void* p) {
    uint32_t a;
    asm("{ .reg .u64 t; cvta.to.shared.u64 t, %1; cvt.u32.u64 %0, t; }"
        : "=r"(a) : "l"(p));
    return a;
}
__device__ __forceinline__ void cp16(uint32_t dst, const void* src) {
    asm volatile("cp.async.cg.shared.global [%0], [%1], 16;"
                 :: "r"(dst), "l"(src) : "memory");
}
__device__ __forceinline__ void cp_commit() {
    asm volatile("cp.async.commit_group;" ::: "memory");
}
__device__ __forceinline__ void cp_wait0() {
    asm volatile("cp.async.wait_group 0;" ::: "memory");
}
__device__ __forceinline__ void barg(int id) {
    asm volatile("bar.sync %0, 128;" :: "r"(id) : "memory");
}
__device__ __forceinline__ void ldsm4(uint32_t* r, uint32_t addr) {
    asm volatile("ldmatrix.sync.aligned.m8n8.x4.shared.b16 {%0,%1,%2,%3}, [%4];"
                 : "=r"(r[0]), "=r"(r[1]), "=r"(r[2]), "=r"(r[3]) : "r"(addr));
}
__device__ __forceinline__ void mma_f16(float* d, const uint32_t* a, const uint32_t* b) {
    asm volatile(
        "mma.sync.aligned.m16n8k16.row.col.f32.f16.f16.f32 "
        "{%0,%1,%2,%3}, {%4,%5,%6,%7}, {%8,%9}, {%0,%1,%2,%3};"
        : "+f"(d[0]), "+f"(d[1]), "+f"(d[2]), "+f"(d[3])
        : "r"(a[0]), "r"(a[1]), "r"(a[2]), "r"(a[3]), "r"(b[0]), "r"(b[1]));
}
// branchless packed top-4 insert: p = (float_bits << 32) | index.
// dists are all >> 0 so unsigned u64 order == (value, index) lexicographic.
__device__ __forceinline__ void t4ins(unsigned long long* t, unsigned long long p) {
    unsigned long long a0 = p  < t[0] ? p    : t[0];
    unsigned long long b0 = p  < t[0] ? t[0] : p;
    t[0] = a0;
    unsigned long long a1 = b0 < t[1] ? b0   : t[1];
    unsigned long long b1 = b0 < t[1] ? t[1] : b0;
    t[1] = a1;
    unsigned long long a2 = b1 < t[2] ? b1   : t[2];
    unsigned long long b2 = b1 < t[2] ? t[2] : b1;
    t[2] = a2;
    t[3] = b2 < t[3] ? b2 : t[3];
}

// ---------------------------------------------------------------------------
// prep: codebook hi fp16 image + ||k||^2 (strict sequential, spread across
// all blocks) + zeroing
// ---------------------------------------------------------------------------
__global__ void prep_kernel(const float* __restrict__ w) {
    const int oct = blockIdx.x * 256 + threadIdx.x;   // 0..32767
    {
        int n = oct >> 4, k0 = (oct & 15) << 3;
        const float* src = w + (size_t)n * D_DIM + k0;
        __align__(16) __half hi[8];
#pragma unroll
        for (int j = 0; j < 8; j++) hi[j] = __float2half_rn(src[j]);
        uint32_t off = (uint32_t)n * ROW_PITCH + (uint32_t)k0 * 2;
        *(uint4*)(g_wsplit + off) = *(uint4*)hi;
    }
    // l2k: 16 rows per block, spread over all 128 blocks (same per-row math)
    if (threadIdx.x < 16) {
        int row = blockIdx.x * 16 + threadIdx.x;
        const float* wr = w + (size_t)row * D_DIM;
        float s = 0.f;
        for (int i = 0; i < D_DIM; i++)
            s = __fadd_rn(s, __fmul_rn(wr[i], wr[i]));   // strict sequential
        g_l2k[row] = s;
    }
    if (oct < M_CB) g_counts[oct] = 0;
    if (oct == 0)   g_loss = 0.f;
}

// ---------------------------------------------------------------------------
// each 128-thread group loads ONLY its own 32-row half of a B tile (hi split)
__device__ __forceinline__ void load_b_half(uint32_t sb, int buf, int nt,
                                            int grp, int gt) {
    const unsigned char* src = g_wsplit + (size_t)nt * B_SPLIT + (size_t)grp * B_HALF;
    uint32_t dst = sb + SM_AB + (uint32_t)buf * B_BUF + (uint32_t)grp * B_HALF;
    for (int i = gt; i < (int)(B_HALF / 16); i += 128)
        cp16(dst + (uint32_t)i * 16u, src + (size_t)i * 16);
}

__device__ __forceinline__ float exact_dist(const float* __restrict__ xrow,
                                            const float* __restrict__ w,
                                            int n, float l2q, float l2k) {
    const float4* wr = (const float4*)(w + (size_t)n * D_DIM);
    const float4* xr = (const float4*)xrow;
    float ps = 0.f;
#pragma unroll
    for (int i = 0; i < 32; i++) {
        float4 a = xr[i], b = wr[i];
        ps = __fmaf_rn(a.x, b.x, ps);
        ps = __fmaf_rn(a.y, b.y, ps);
        ps = __fmaf_rn(a.z, b.z, ps);
        ps = __fmaf_rn(a.w, b.w, ps);
    }
    return __fmaf_rn(-2.f, ps, __fadd_rn(l2q, l2k));
}

// ---------------------------------------------------------------------------
// main: M=64 query tile per CTA, 256 threads (8 warps, 4(M) x 2(N)),
// 2 CTAs/SM. hh-only fp16 HMMA sweep, PAIRED tiles per sync (one
// cp_wait+barrier per 2 tiles -> envelope halved, registers unchanged);
// per-thread top-4 capture per row-half; exact fp32 refine; epilogue.
// ---------------------------------------------------------------------------
__global__ __launch_bounds__(256, 2)
void vq_main_kernel(const float* __restrict__ x, const float* __restrict__ w,
                    float* __restrict__ out)
{
    extern __shared__ char smem[];
    const uint32_t sb = smem_to_u32(smem);
    const int tid = threadIdx.x;
    const int wid = tid >> 5, l = tid & 31;
    const int wx = wid & 3, wy = wid >> 2;        // wx: M (4 x 16 rows), wy: N group
    const int lq = l >> 2, lr = l & 3;
    const int m0 = blockIdx.x * 64;
    const int grp = wy;                            // group id == tid>>7
    const int gt  = tid & 127;                     // thread id within group
    const int phase = (blockIdx.x & 1) << 4;       // co-resident CTA stagger (16 of 32)

    float* l2k_s  = (float*)(smem + SM_L2K);
    float* l2q_s  = (float*)(smem + SM_L2Q);
    unsigned long long* cand = (unsigned long long*)(smem + SM_CAND);  // [64][32]
    int*   best_s = (int*)  (smem + SM_BEST);
    float* wsum   = (float*)(smem + SM_WSUM);

    // ---- build A hi image (fp16) in B-buf0 region (overlay)
#pragma unroll
    for (int i = 0; i < 4; i++) {
        int idx = tid + (i << 8);               // 0..1023 octets (64 rows x 16)
        int r = idx >> 4, k0 = (idx & 15) << 3;
        const float4* src = (const float4*)(x + (size_t)(m0 + r) * D_DIM + k0);
        float4 v0 = src[0], v1 = src[1];
        float vv[8] = {v0.x, v0.y, v0.z, v0.w, v1.x, v1.y, v1.z, v1.w};
        __align__(16) __half hi[8];
#pragma unroll
        for (int j = 0; j < 8; j++) hi[j] = __float2half_rn(vv[j]);
        uint32_t off = SM_AB + (uint32_t)r * ROW_PITCH + (uint32_t)k0 * 2;
        *(uint4*)(smem + off) = *(uint4*)hi;
    }
    // ---- stage l2k (512 float4 = 2048 floats)
    ((float4*)l2k_s)[tid]       = ((const float4*)g_l2k)[tid];
    ((float4*)l2k_s)[tid + 256] = ((const float4*)g_l2k)[tid + 256];
    // ---- l2q per row: strict sequential fp32 (reference rounding)
    if (tid < 64) {
        const float* xr = x + (size_t)(m0 + tid) * D_DIM;
        float s = 0.f;
        for (int k = 0; k < D_DIM; k++)
            s = __fadd_rn(s, __fmul_rn(xr[k], xr[k]));
        l2q_s[tid] = s;
    }
    __syncthreads();     // A image visible

    // ---- load A fragments ONCE (register-resident: 8 chunks x 4 regs)
    uint32_t aF[8][4];
    {
        uint32_t row = (uint32_t)(wx * 16) + (uint32_t)(l & 15);
        uint32_t kbl = (uint32_t)((l >> 4) & 1) * 16u;
        uint32_t base = sb + SM_AB + row * ROW_PITCH + kbl;
#pragma unroll
        for (int c = 0; c < 8; c++)
            ldsm4(aF[c], base + (uint32_t)c * 32u);
    }
    float lqr[2];
    lqr[0] = l2q_s[wx * 16 + lq];
    lqr[1] = l2q_s[wx * 16 + lq + 8];
    __syncthreads();     // A image consumed -> buf0 free for B

    // first tile PAIR (phase-staggered) into buf0,buf1; single commit group
    load_b_half(sb, 0, phase, grp, gt);
    load_b_half(sb, 1, (phase + 1) & 31, grp, gt);
    cp_commit();

    // B lane base (within own group's half); buf offset added per tile
    uint32_t bBase;
    {
        uint32_t row = (uint32_t)(wy * 32) + (uint32_t)(l & 7) + (uint32_t)((l >> 4) & 1) * 8u;
        uint32_t kbl = (uint32_t)((l >> 3) & 1) * 16u;
        bBase = sb + SM_AB + row * ROW_PITCH + kbl;
    }

    // per-thread top-4 per row-half
    unsigned long long t4[2][4];
#pragma unroll
    for (int h = 0; h < 2; h++)
#pragma unroll
        for (int j = 0; j < 4; j++) t4[h][j] = U64MAX;
    float f4[2] = {3.0e38f, 3.0e38f};   // fp32 shadow of 4th-best values

    for (int p = 0; p < NUM_PAIRS; p++) {
        cp_wait0();          // this pair's tiles arrived
        barg(1 + grp);       // group-local: data visible; group done with the
                             // buffer pair about to be overwritten below
        if (p + 1 < NUM_PAIRS) {
            const int nb = ((p + 1) & 1) * 2;
            const int tb = (2 * (p + 1) + phase) & 31;
            load_b_half(sb, nb,     tb,            grp, gt);
            load_b_half(sb, nb + 1, (tb + 1) & 31, grp, gt);
            cp_commit();
        }

#pragma unroll
        for (int half = 0; half < 2; half++) {
            const int nt = (2 * p + half + phase) & 31;   // actual tile id
            const uint32_t bOff = (uint32_t)((p & 1) * 2 + half) * B_BUF;

            float acc[4][4];
#pragma unroll
            for (int n8 = 0; n8 < 4; n8++)
#pragma unroll
                for (int q = 0; q < 4; q++) acc[n8][q] = 0.f;

#pragma unroll
            for (int c = 0; c < 8; c++) {
                const uint32_t kb = (uint32_t)c * 32u;
                uint32_t bF[2][4];    // [ni16][reg]
#pragma unroll
                for (int g = 0; g < 2; g++)
                    ldsm4(bF[g], bBase + bOff + (uint32_t)g * (16u * ROW_PITCH) + kb);
#pragma unroll
                for (int n8 = 0; n8 < 4; n8++)
                    mma_f16(acc[n8], aF[c], &bF[n8 >> 1][(n8 & 1) * 2]);
            }

            // epilogue: 16 dists -> per-half tile-min guard -> rare top-4
            // insert. Skip is exact: all v > f4 strictly implies every packed
            // key > t[3] (positive-float bit monotonicity) -> inserts no-ops.
            {
                float vv0[8], vv1[8];
#pragma unroll
                for (int n8 = 0; n8 < 4; n8++) {
                    const int col0 = nt * 64 + wy * 32 + n8 * 8 + (lr << 1);
                    const float2 lk = *(const float2*)(l2k_s + col0);
                    vv0[n8 * 2 + 0] = __fmaf_rn(-2.f, acc[n8][0], __fadd_rn(lqr[0], lk.x));
                    vv0[n8 * 2 + 1] = __fmaf_rn(-2.f, acc[n8][1], __fadd_rn(lqr[0], lk.y));
                    vv1[n8 * 2 + 0] = __fmaf_rn(-2.f, acc[n8][2], __fadd_rn(lqr[1], lk.x));
                    vv1[n8 * 2 + 1] = __fmaf_rn(-2.f, acc[n8][3], __fadd_rn(lqr[1], lk.y));
                }
                float tm0 = vv0[0], tm1 = vv1[0];
#pragma unroll
                for (int j = 1; j < 8; j++) {
                    tm0 = fminf(tm0, vv0[j]);
                    tm1 = fminf(tm1, vv1[j]);
                }
                const int base = nt * 64 + wy * 32 + (lr << 1);
                if (tm0 <= f4[0]) {
#pragma unroll
                    for (int j = 0; j < 8; j++) {
                        unsigned n = (unsigned)(base + ((j >> 1) << 3) + (j & 1));
                        unsigned long long pk =
                            ((unsigned long long)__float_as_uint(vv0[j]) << 32) | n;
                        t4ins(t4[0], pk);
                    }
                    f4[0] = __uint_as_float((uint32_t)(t4[0][3] >> 32));
                }
                if (tm1 <= f4[1]) {
#pragma unroll
                    for (int j = 0; j < 8; j++) {
                        unsigned n = (unsigned)(base + ((j >> 1) << 3) + (j & 1));
                        unsigned long long pk =
                            ((unsigned long long)__float_as_uint(vv1[j]) << 32) | n;
                        t4ins(t4[1], pk);
                    }
                    f4[1] = __uint_as_float((uint32_t)(t4[1][3] >> 32));
                }
            }
        }
        // no trailing barrier: next iteration's group barrier protects reuse
    }

    // ---- write per-thread top-4 candidates (no lane merge: keep all 32/row)
#pragma unroll
    for (int h = 0; h < 2; h++) {
        int row = wx * 16 + h * 8 + lq;
        unsigned long long* dst = cand + row * 32 + wy * 16 + lr * 4;
#pragma unroll
        for (int j = 0; j < 4; j++) dst[j] = t4[h][j];
    }
    __syncthreads();    // both groups' cand slots visible

    // ---- per-row final scan: approx top-2 gap test + exact fp32 refine
    if (tid < 64) {
        unsigned long long b1 = U64MAX, b2 = U64MAX;
        const unsigned long long* cr = cand + tid * 32;
#pragma unroll
        for (int j = 0; j < 32; j++) {
            unsigned long long p = cr[j];
            unsigned long long mx = p > b1 ? p : b1;
            b1 = p < b1 ? p : b1;
            b2 = mx < b2 ? mx : b2;
        }
        float v1 = __uint_as_float((uint32_t)(b1 >> 32));
        float v2 = __uint_as_float((uint32_t)(b2 >> 32));
        int best = (int)(uint32_t)(b1 & 0xFFFFFFFFu);
        if (v2 - v1 <= MARGIN) {
            const float* xrow = x + (size_t)(m0 + tid) * D_DIM;
            const float l2q_r = l2q_s[tid];
            float bd = 3.0e38f;
            int   bi = 0x7fffffff;
#pragma unroll 1
            for (int j = 0; j < 32; j++) {
                unsigned long long p = cr[j];
                float pv = __uint_as_float((uint32_t)(p >> 32));
                if (pv <= v1 + MARGIN) {
                    int n = (int)(uint32_t)(p & 0xFFFFFFFFu);
                    float d = exact_dist(xrow, w, n, l2q_r, l2k_s[n]);
                    if (d < bd || (d == bd && n < bi)) { bd = d; bi = n; }
                }
            }
            best = bi;
        }
        best_s[tid] = best;
        atomicAdd(&g_counts[best], 1);
        out[IDX_OFF + m0 + tid] = (float)best;
    }
    __syncthreads();

    // ---- gather z, quantized_st = x + (z - x), loss partial (quarter-row/thread)
    {
        const int r  = tid >> 2;
        const int kb = (tid & 3) << 5;
        const int best = best_s[r];
        const float4* xr = (const float4*)(x + (size_t)(m0 + r) * D_DIM + kb);
        const float4* wz = (const float4*)(w + (size_t)best * D_DIM + kb);
        float4* oq = (float4*)(out + (size_t)(m0 + r) * D_DIM + kb);
        float lsum = 0.f;
#pragma unroll
        for (int i = 0; i < 8; i++) {
            float4 xv = xr[i], z = wz[i];
            float4 qv;
            qv.x = __fadd_rn(xv.x, __fsub_rn(z.x, xv.x));
            qv.y = __fadd_rn(xv.y, __fsub_rn(z.y, xv.y));
            qv.z = __fadd_rn(xv.z, __fsub_rn(z.z, xv.z));
            qv.w = __fadd_rn(xv.w, __fsub_rn(z.w, xv.w));
            oq[i] = qv;
            float d0 = __fsub_rn(qv.x, xv.x), d1 = __fsub_rn(qv.y, xv.y);
            float d2 = __fsub_rn(qv.z, xv.z), d3 = __fsub_rn(qv.w, xv.w);
            lsum += d0 * d0 + d1 * d1 + d2 * d2 + d3 * d3;
        }
#pragma unroll
        for (int o = 16; o > 0; o >>= 1)
            lsum += __shfl_down_sync(0xffffffffu, lsum, o);
        if ((tid & 31) == 0) wsum[wid] = lsum;
    }
    __syncthreads();
    if (tid == 0) {
        float s = 0.f;
#pragma unroll
        for (int i = 0; i < 8; i++) s += wsum[i];
        atomicAdd(&g_loss, s);
    }
}

// ---------------------------------------------------------------------------
// finalize: loss mean + perplexity
// ---------------------------------------------------------------------------
__global__ void finalize_kernel(float* __restrict__ out) {
    int t = threadIdx.x;
    float s = 0.f;
    for (int i = t; i < M_CB; i += 256) {
        float p = (float)g_counts[i] * (1.0f / 65536.0f);
        s += p * logf(p + 1e-10f);
    }
#pragma unroll
    for (int o = 16; o > 0; o >>= 1)
        s += __shfl_down_sync(0xffffffffu, s, o);
    __shared__ float ws[8];
    if ((t & 31) == 0) ws[t >> 5] = s;
    __syncthreads();
    if (t == 0) {
        float tot = 0.f;
#pragma unroll
        for (int i = 0; i < 8; i++) tot += ws[i];
        out[LOSS_OFF] = g_loss * (1.0f / 8388608.0f);
        out[PERP_OFF] = expf(-tot);
    }
}

// ---------------------------------------------------------------------------
extern "C" void kernel_launch(void* const* d_in, const int* in_sizes, int n_in,
                              void* d_out, int out_size) {
    const float* x = (const float*)d_in[0];
    const float* w = (const float*)d_in[1];
    if (n_in >= 2 && in_sizes[0] == M_CB * D_DIM && in_sizes[1] == Q_ELEMS) {
        x = (const float*)d_in[1];
        w = (const float*)d_in[0];
    }
    float* out = (float*)d_out;

    cudaFuncSetAttribute(vq_main_kernel,
                         cudaFuncAttributeMaxDynamicSharedMemorySize, SM_TOTAL);

    prep_kernel<<<128, 256>>>(w);
    vq_main_kernel<<<BN_TOTAL / 64, 256, SM_TOTAL>>>(x, w, out);
    finalize_kernel<<<1, 256>>>(out);
}